// round 14
// baseline (speedup 1.0000x reference)
#include <cuda_runtime.h>
#include <cstdint>

#define B_SZ  8
#define SEQ   4096
#define HID   1024
#define HID2  (HID / 2)
#define HID4  (HID / 4)
#define DMAX  16             // FIR truncation: g[d] <= 0.64*0.16^d -> 4e-13 at d=16
#define CHUNKS 16            // time-chunks; block = (b, chunk) covers full h-row
#define CGRP   8             // stored 32-step groups per chunk
#define WGRP   6             // warmup groups (192 steps): 0.9^192 ~ 1.7e-9
#define NTH    544           // warp 0 = g/FIR specialist, warps 1..16 = 512 scan

// ---------------- LIF step: float-mask form (masks exactly 0.0/1.0) --------------
// w09 = rn(0.9 * v_pre-reset), ns = 1-spike_prev, act = (r<=0), r exact int.
// Every FFMA multiplies by exact 0/1 so rounding == reference's mul+add.
struct SnnState { float w09, ns, act, r; };

__device__ __forceinline__ void snn_step(SnnState& st, float xk,
                                         float& macc, float mc)
{
    float v1 = __fmaf_rn(st.w09, st.ns, xk);          // rn(0.9*v_post + x)
    float ge; asm("set.ge.f32.f32 %0, %1, %2;" : "=f"(ge) : "f"(v1), "f"(1.0f));
    float s  = __fmul_rn(ge, st.act);                 // spike as 0.0/1.0
    st.w09   = __fmul_rn(v1, 0.9f);
    st.ns    = __fmaf_rn(-ge, st.act, 1.0f);          // 1 - spike (exact)
    float rd = fmaxf(__fadd_rn(st.r, -1.0f), 0.0f);   // max(r-1,0), exact
    st.r     = __fmaf_rn(s, 5.0f, rd);                // spike => rd==0 => 5
    asm("set.le.f32.f32 %0, %1, %2;" : "=f"(st.act) : "f"(st.r), "f"(0.0f));
    macc     = __fmaf_rn(s, mc, macc);                // exact bit accumulation
}

// ---------------- single fused kernel: g + scan + u + y(FIR) + write -------------
// 128 blocks of 544 threads: block = (b, chunk) owns the FULL 1024-h row for its
// 256-step stored range (+192-step warmup). Warp 0 NEVER scans: it computes the
// SSM impulse response g[d]=C A^d B with only __syncwarp (no block barriers),
// then serves as the u/FIR warp each epilogue. Warps 1-16 (512 threads, 2 h
// lanes each) scan and never wait on g. 3 block barriers per epilogue group.
__global__ void __launch_bounds__(NTH) fused_kernel(const float* __restrict__ x,
                                                    const float* __restrict__ Ap,
                                                    const float* __restrict__ Bp,
                                                    const float* __restrict__ Cp,
                                                    const float* __restrict__ Dp,
                                                    float* __restrict__ out)
{
    __shared__ float As[64 * 65];        // A rows padded (warp 0 only)
    __shared__ float wping[2][64];       // Krylov ping-pong
    __shared__ float g_s[DMAX];
    __shared__ unsigned wsm[2][HID];     // double-buffered group masks
    __shared__ int   part[16 * 32];      // per-scan-warp partial popcounts
    __shared__ float u_s[64];            // [0..31]=prev group u, [32..63]=cur
    __shared__ float y_s[32], y1_s[32];

    const int blk  = blockIdx.x;         // 0..127
    const int c    = blk & (CHUNKS - 1);
    const int b    = blk >> 4;
    const int tid  = threadIdx.x;        // 0..543
    const int wid  = tid >> 5, lane = tid & 31;
    const int st   = (tid >= 32) ? (tid - 32) : 0;   // scan-thread index 0..511
    const int h    = st * 2;             // 2 hidden lanes per scan thread

    const int warm    = c ? WGRP : 0;
    const int g0      = c * CGRP;
    const int tbegin  = (g0 - warm) * 32;
    const int ngroups = warm + CGRP;     // 8 or 14

    const float2* xp = (const float2*)(x + ((size_t)b * SEQ + tbegin) * HID) + st;
    float4* out4 = (float4*)(out + ((size_t)b * SEQ + g0 * 32) * HID);
    const float Ds = __ldg(Dp);

    // scan warps: issue the x prefetch immediately (DRAM ramps at once)
    float2 buf[32];
    if (wid > 0) {
        #pragma unroll
        for (int i = 0; i < 32; i++) buf[i] = xp[(size_t)i * HID2];
    }
    const float2* xld = xp + (size_t)32 * HID2;

    // ---- warp 0: g[d] = C . (A^d B), __syncwarp only --------------------------
    if (wid == 0) {
        u_s[lane] = 0.0f;                              // halo for chunk 0
        for (int k = lane; k < 1024; k += 32) {        // A: 1024 float4 loads
            float4 v = ((const float4*)Ap)[k];
            int r = k >> 4, s4 = (k & 15) * 4;
            As[r * 65 + s4 + 0] = v.x;
            As[r * 65 + s4 + 1] = v.y;
            As[r * 65 + s4 + 2] = v.z;
            As[r * 65 + s4 + 3] = v.w;
        }
        const int r0 = lane * 2, r1 = lane * 2 + 1;
        const float c0 = Cp[r0], c1 = Cp[r1];
        float w0 = Bp[r0], w1 = Bp[r1];
        wping[0][r0] = w0;
        wping[0][r1] = w1;
        float p = __fmaf_rn(c1, w1, __fmul_rn(c0, w0));   // g[0] = C.B
        #pragma unroll
        for (int o = 16; o; o >>= 1) p += __shfl_xor_sync(0xffffffffu, p, o);
        if (lane == 0) g_s[0] = p;
        __syncwarp();
        for (int d = 1; d < DMAX; d++) {
            const float* wp = wping[(d - 1) & 1];
            float a00=0,a01=0,a02=0,a03=0, a10=0,a11=0,a12=0,a13=0;
            #pragma unroll
            for (int s = 0; s < 64; s += 4) {
                float q0 = wp[s], q1 = wp[s+1], q2 = wp[s+2], q3 = wp[s+3];
                a00 += As[r0*65+s  ]*q0; a01 += As[r0*65+s+1]*q1;
                a02 += As[r0*65+s+2]*q2; a03 += As[r0*65+s+3]*q3;
                a10 += As[r1*65+s  ]*q0; a11 += As[r1*65+s+1]*q1;
                a12 += As[r1*65+s+2]*q2; a13 += As[r1*65+s+3]*q3;
            }
            float wn0 = (a00+a01)+(a02+a03);
            float wn1 = (a10+a11)+(a12+a13);
            float pd = __fmaf_rn(c1, wn1, __fmul_rn(c0, wn0));
            #pragma unroll
            for (int o = 16; o; o >>= 1) pd += __shfl_xor_sync(0xffffffffu, pd, o);
            if (lane == 0) g_s[d] = pd;
            wping[d & 1][r0] = wn0;
            wping[d & 1][r1] = wn1;
            __syncwarp();
        }
    }

    // ---- main loop: scan (warps 1-16) + epilogue --------------------------------
    SnnState s0 = {0,1,1,0}, s1 = {0,1,1,0};

    for (int gg = 0; gg < ngroups; gg++) {
        uint2 mv = {0u, 0u};
        if (wid > 0) {
            const bool pf = (gg + 1 < ngroups);
            float m0l = 0, m0h = 0, m1l = 0, m1h = 0;
            #pragma unroll
            for (int i = 0; i < 32; i++) {
                float2 xk = buf[i];
                if (pf) buf[i] = xld[(size_t)i * HID2];   // prefetch next group
                const float mc = (float)(1u << (i & 15));
                if (i < 16) { snn_step(s0, xk.x, m0l, mc); snn_step(s1, xk.y, m1l, mc); }
                else        { snn_step(s0, xk.x, m0h, mc); snn_step(s1, xk.y, m1h, mc); }
            }
            xld += (size_t)32 * HID2;
            mv.x = __float2uint_rn(m0l) | (__float2uint_rn(m0h) << 16);
            mv.y = __float2uint_rn(m1l) | (__float2uint_rn(m1h) << 16);
        }

        if (gg < warm - 1) continue;      // uniform per block

        unsigned* wcur = wsm[gg & 1];     // double buffer
        if (wid > 0) *(uint2*)&wcur[h] = mv;
        __syncthreads();                  // B1: wsm ready

        if (wid > 0) {                    // popcount transpose: 16 scan warps
            int cnt = 0;
            #pragma unroll 16
            for (int i2 = 0; i2 < 64; i2++)
                cnt += (int)((wcur[(wid - 1) * 64 + i2] >> lane) & 1u);
            part[(wid - 1) * 32 + lane] = cnt;
        }
        __syncthreads();                  // B2: part ready

        if (wid == 0) {                   // u, then FIR y (race-free: __syncwarp)
            int tot = 0;
            #pragma unroll
            for (int w2 = 0; w2 < 16; w2++) tot += part[w2 * 32 + lane];
            float uv = (float)tot * (1.0f / (float)HID);
            u_s[32 + lane] = uv;
            __syncwarp();                 // u_s visible across warp-0 lanes
            if (gg >= warm) {
                float acc = Ds * uv;      // y = D*u + g (*) u
                #pragma unroll
                for (int d = 0; d < DMAX; d++)
                    acc += g_s[d] * u_s[32 + lane - d];
                y_s[lane]  = acc;
                y1_s[lane] = acc + 1.0f;
            }
            __syncwarp();                 // FIR reads done before slide
            u_s[lane] = u_s[32 + lane];   // slide cur -> prev
        }
        __syncthreads();                  // B3: y ready

        if (wid > 0 && gg >= warm) {
            // write 32 t x 1024 h: thread = (quad q, t-half hf); STG.128
            const int q  = st & 255;
            const int hf = st >> 8;
            const uint4 w4 = ((const uint4*)wcur)[q];
            float4* rowb = out4 + (size_t)(gg - warm) * 32 * HID4 + q;
            #pragma unroll
            for (int k = 0; k < 16; k++) {
                const int t = hf * 16 + k;
                const float y = y_s[t], y1 = y1_s[t];
                float4 o;
                o.x = ((w4.x >> t) & 1u) ? y1 : y;
                o.y = ((w4.y >> t) & 1u) ? y1 : y;
                o.z = ((w4.z >> t) & 1u) ? y1 : y;
                o.w = ((w4.w >> t) & 1u) ? y1 : y;
                __stcs(&rowb[(size_t)t * HID4], o);
            }
        }
    }
}

// ---------------- launch ----------------------------------------------------------
extern "C" void kernel_launch(void* const* d_in, const int* in_sizes, int n_in,
                              void* d_out, int out_size)
{
    const float* x  = (const float*)d_in[0];   // (8, 4096, 1024) f32
    const float* A  = (const float*)d_in[1];   // (64, 64)
    const float* Bv = (const float*)d_in[2];   // (64, 1)
    const float* Cv = (const float*)d_in[3];   // (1, 64)
    const float* Dp = (const float*)d_in[4];   // (1, 1)

    fused_kernel<<<B_SZ * CHUNKS, NTH>>>(x, A, Bv, Cv, Dp, (float*)d_out);
}

// round 15
// speedup vs baseline: 1.0621x; 1.0621x over previous
#include <cuda_runtime.h>
#include <cstdint>

#define B_SZ  8
#define SEQ   4096
#define HID   1024
#define HID2  (HID / 2)
#define HID4  (HID / 4)
#define DMAX  16             // FIR truncation: g[d] <= 0.64*0.16^d -> 4e-13 at d=16
#define CHUNKS 16            // time-chunks; block = (b, chunk) covers full h-row
#define CGRP   8             // stored 32-step groups per chunk
#define WGRP   6             // warmup groups (192 steps): 0.9^192 ~ 1.7e-9

// ---------------- LIF step: float-mask form (masks exactly 0.0/1.0) --------------
// w09 = rn(0.9 * v_pre-reset), ns = 1-spike_prev, act = (r<=0), r exact int.
// Every FFMA multiplies by exact 0/1 so rounding == reference's mul+add.
struct SnnState { float w09, ns, act, r; };

__device__ __forceinline__ void snn_step(SnnState& st, float xk,
                                         float& macc, float mc)
{
    float v1 = __fmaf_rn(st.w09, st.ns, xk);          // rn(0.9*v_post + x)
    float ge; asm("set.ge.f32.f32 %0, %1, %2;" : "=f"(ge) : "f"(v1), "f"(1.0f));
    float s  = __fmul_rn(ge, st.act);                 // spike as 0.0/1.0
    st.w09   = __fmul_rn(v1, 0.9f);
    st.ns    = __fmaf_rn(-ge, st.act, 1.0f);          // 1 - spike (exact)
    float rd = fmaxf(__fadd_rn(st.r, -1.0f), 0.0f);   // max(r-1,0), exact
    st.r     = __fmaf_rn(s, 5.0f, rd);                // spike => rd==0 => 5
    asm("set.le.f32.f32 %0, %1, %2;" : "=f"(st.act) : "f"(st.r), "f"(0.0f));
    macc     = __fmaf_rn(s, mc, macc);                // exact bit accumulation
}

// ---------------- single fused kernel: g + scan + u + y(FIR) + write -------------
// 128 blocks of 512 threads: block = (b, chunk) owns the FULL 1024-h row for its
// 256-step stored range (+192-step warmup). Short g prologue (16 light barriers),
// then a software-pipelined main loop with TWO barriers per epilogue group:
//   iter gg:  scan gg -> store masks -> B1 -> write OUT for gg-1 (y ready)
//             -> popcount transpose gg -> B2 -> FIR warp computes y_gg
// The FIR (one rotating warp) overlaps the other warps' next scan. Drain at end.
__global__ void __launch_bounds__(512) fused_kernel(const float* __restrict__ x,
                                                    const float* __restrict__ Ap,
                                                    const float* __restrict__ Bp,
                                                    const float* __restrict__ Cp,
                                                    const float* __restrict__ Dp,
                                                    float* __restrict__ out)
{
    __shared__ float As[64 * 65];        // A rows padded
    __shared__ float Wall[DMAX][64];     // Krylov vectors A^d B
    __shared__ float wping[2][64];
    __shared__ float cs[64];
    __shared__ float g_s[DMAX];
    __shared__ unsigned wsm[2][HID];     // double-buffered group masks
    __shared__ int   part[16 * 32];      // per-warp partial popcounts
    __shared__ float u_lin[48];          // [0..15]=tail of prev group, [16..47]=cur
    __shared__ float y_s[2][32], y1_s[2][32];

    const int blk  = blockIdx.x;         // 0..127
    const int c    = blk & (CHUNKS - 1);
    const int b    = blk >> 4;
    const int tid  = threadIdx.x;        // 0..511
    const int wid  = tid >> 5, lane = tid & 31;
    const int h    = tid * 2;            // 2 hidden lanes per thread

    const int warm    = c ? WGRP : 0;
    const int g0      = c * CGRP;
    const int tbegin  = (g0 - warm) * 32;
    const int ngroups = warm + CGRP;     // 8 or 14

    const float2* xp = (const float2*)(x + ((size_t)b * SEQ + tbegin) * HID) + tid;
    float4* out4 = (float4*)(out + ((size_t)b * SEQ + g0 * 32) * HID);
    const float Ds = __ldg(Dp);

    // issue the x prefetch FIRST so DRAM ramps under the g prologue.
    float2 buf[32];
    #pragma unroll
    for (int i = 0; i < 32; i++) buf[i] = xp[(size_t)i * HID2];
    const float2* xld = xp + (size_t)32 * HID2;

    // ---- g prologue: W_0=B; W_d=A W_{d-1}; g[d]=C.W_d (16 light barriers) -------
    for (int i = tid; i < 64 * 64; i += 512)
        As[(i >> 6) * 65 + (i & 63)] = Ap[i];
    if (tid < 64) {
        cs[tid] = Cp[tid];
        float b0 = Bp[tid];
        wping[0][tid] = b0;
        Wall[0][tid]  = b0;
    }
    if (tid >= 64 && tid < 80) u_lin[tid - 64] = 0.0f;   // halo for chunk 0
    __syncthreads();
    {
        const int row = tid >> 3, sub = tid & 7;         // 8 threads per row
        for (int d = 1; d < DMAX; d++) {
            const float* wprev = wping[(d - 1) & 1];
            float p = 0.f;
            #pragma unroll
            for (int j = 0; j < 8; j++)
                p += As[row * 65 + sub * 8 + j] * wprev[sub * 8 + j];
            p += __shfl_xor_sync(0xffffffffu, p, 1);
            p += __shfl_xor_sync(0xffffffffu, p, 2);
            p += __shfl_xor_sync(0xffffffffu, p, 4);
            if (sub == 0) { wping[d & 1][row] = p; Wall[d][row] = p; }
            __syncthreads();
        }
        if (tid < DMAX * 8) {                            // all 16 dots in parallel
            const int d = tid >> 3, s8 = (tid & 7) * 8;
            float p = 0.f;
            #pragma unroll
            for (int j = 0; j < 8; j++) p += cs[s8 + j] * Wall[d][s8 + j];
            p += __shfl_xor_sync(0xffffffffu, p, 1);
            p += __shfl_xor_sync(0xffffffffu, p, 2);
            p += __shfl_xor_sync(0xffffffffu, p, 4);
            if ((tid & 7) == 0) g_s[d] = p;
        }
        __syncthreads();
    }

    // ---- pipelined main loop ------------------------------------------------------
    SnnState s0 = {0,1,1,0}, s1 = {0,1,1,0};

    for (int gg = 0; gg < ngroups; gg++) {
        const bool pf = (gg + 1 < ngroups);
        float m0l = 0, m0h = 0, m1l = 0, m1h = 0;
        #pragma unroll
        for (int i = 0; i < 32; i++) {
            float2 xk = buf[i];
            if (pf) buf[i] = xld[(size_t)i * HID2];      // prefetch next group
            const float mc = (float)(1u << (i & 15));
            if (i < 16) { snn_step(s0, xk.x, m0l, mc); snn_step(s1, xk.y, m1l, mc); }
            else        { snn_step(s0, xk.x, m0h, mc); snn_step(s1, xk.y, m1h, mc); }
        }
        xld += (size_t)32 * HID2;

        if (gg < warm - 1) continue;                     // uniform per block

        unsigned* wcur = wsm[gg & 1];                    // double buffer
        uint2 mv;
        mv.x = __float2uint_rn(m0l) | (__float2uint_rn(m0h) << 16);
        mv.y = __float2uint_rn(m1l) | (__float2uint_rn(m1h) << 16);
        *(uint2*)&wcur[h] = mv;
        __syncthreads();                                 // B1: wsm[gg] + y[gg-1] ready

        if (gg - 1 >= warm) {                            // write OUT for group gg-1
            const unsigned* wprev = wsm[(gg - 1) & 1];
            const float* yb  = y_s[(gg - 1) & 1];
            const float* y1b = y1_s[(gg - 1) & 1];
            const int q  = tid & 255;
            const int hf = tid >> 8;
            const uint4 w4 = ((const uint4*)wprev)[q];
            float4* rowb = out4 + (size_t)(gg - 1 - warm) * 32 * HID4 + q;
            #pragma unroll
            for (int k = 0; k < 16; k++) {
                const int t = hf * 16 + k;
                const float y = yb[t], y1 = y1b[t];
                float4 o;
                o.x = ((w4.x >> t) & 1u) ? y1 : y;
                o.y = ((w4.y >> t) & 1u) ? y1 : y;
                o.z = ((w4.z >> t) & 1u) ? y1 : y;
                o.w = ((w4.w >> t) & 1u) ? y1 : y;
                __stcs(&rowb[(size_t)t * HID4], o);
            }
        }

        {   // popcount transpose of group gg (16 warps x 64 words)
            int cnt = 0;
            #pragma unroll 16
            for (int i2 = 0; i2 < 64; i2++)
                cnt += (int)((wcur[wid * 64 + i2] >> lane) & 1u);
            part[wid * 32 + lane] = cnt;
        }
        __syncthreads();                                 // B2: part ready

        if (wid == (gg & 15)) {                          // rotating FIR warp
            int tot = 0;
            #pragma unroll
            for (int w2 = 0; w2 < 16; w2++) tot += part[w2 * 32 + lane];
            float uv = (float)tot * (1.0f / (float)HID);
            u_lin[16 + lane] = uv;
            __syncwarp();                                // u_lin visible warp-wide
            if (gg >= warm) {
                float acc = Ds * uv;                     // y = D*u + g (*) u
                #pragma unroll
                for (int d = 0; d < DMAX; d++)
                    acc += g_s[d] * u_lin[16 + lane - d];
                y_s[gg & 1][lane]  = acc;
                y1_s[gg & 1][lane] = acc + 1.0f;
            }
            __syncwarp();                                // taps read before slide
            if (lane < 16) u_lin[lane] = u_lin[32 + lane];   // slide tail
        }
        // NO third barrier: FIR overlaps the other warps' next scan group.
    }

    // ---- drain: write OUT for the final group -----------------------------------
    __syncthreads();                                     // y[last] ready
    {
        const int lg = ngroups - 1;                      // always >= warm
        const unsigned* wprev = wsm[lg & 1];
        const float* yb  = y_s[lg & 1];
        const float* y1b = y1_s[lg & 1];
        const int q  = tid & 255;
        const int hf = tid >> 8;
        const uint4 w4 = ((const uint4*)wprev)[q];
        float4* rowb = out4 + (size_t)(lg - warm) * 32 * HID4 + q;
        #pragma unroll
        for (int k = 0; k < 16; k++) {
            const int t = hf * 16 + k;
            const float y = yb[t], y1 = y1b[t];
            float4 o;
            o.x = ((w4.x >> t) & 1u) ? y1 : y;
            o.y = ((w4.y >> t) & 1u) ? y1 : y;
            o.z = ((w4.z >> t) & 1u) ? y1 : y;
            o.w = ((w4.w >> t) & 1u) ? y1 : y;
            __stcs(&rowb[(size_t)t * HID4], o);
        }
    }
}

// ---------------- launch ----------------------------------------------------------
extern "C" void kernel_launch(void* const* d_in, const int* in_sizes, int n_in,
                              void* d_out, int out_size)
{
    const float* x  = (const float*)d_in[0];   // (8, 4096, 1024) f32
    const float* A  = (const float*)d_in[1];   // (64, 64)
    const float* Bv = (const float*)d_in[2];   // (64, 1)
    const float* Cv = (const float*)d_in[3];   // (1, 64)
    const float* Dp = (const float*)d_in[4];   // (1, 1)

    fused_kernel<<<B_SZ * CHUNKS, 512>>>(x, A, Bv, Cv, Dp, (float*)d_out);
}

// round 16
// speedup vs baseline: 1.1579x; 1.0902x over previous
#include <cuda_runtime.h>
#include <cstdint>

#define B_SZ  8
#define SEQ   4096
#define HID   1024
#define HID2  (HID / 2)
#define HID4  (HID / 4)
#define DMAX  16             // FIR truncation: g[d] <= 0.64*0.16^d -> 4e-13 at d=16
#define CHUNKS 16            // time-chunks; block = (b, chunk) covers full h-row
#define CGRP   8             // stored 32-step groups per chunk
#define WGRP   6             // warmup groups (192 steps): 0.9^192 ~ 1.7e-9

// ---------------- LIF step: float-mask form (masks exactly 0.0/1.0) --------------
struct SnnState { float w09, ns, act, r; };

__device__ __forceinline__ void snn_step(SnnState& st, float xk,
                                         float& macc, float mc)
{
    float v1 = __fmaf_rn(st.w09, st.ns, xk);          // rn(0.9*v_post + x)
    float ge; asm("set.ge.f32.f32 %0, %1, %2;" : "=f"(ge) : "f"(v1), "f"(1.0f));
    float s  = __fmul_rn(ge, st.act);                 // spike as 0.0/1.0
    st.w09   = __fmul_rn(v1, 0.9f);
    st.ns    = __fmaf_rn(-ge, st.act, 1.0f);          // 1 - spike (exact)
    float rd = fmaxf(__fadd_rn(st.r, -1.0f), 0.0f);   // max(r-1,0), exact
    st.r     = __fmaf_rn(s, 5.0f, rd);                // spike => rd==0 => 5
    asm("set.le.f32.f32 %0, %1, %2;" : "=f"(st.act) : "f"(st.r), "f"(0.0f));
    macc     = __fmaf_rn(s, mc, macc);                // exact bit accumulation
}

// 32x32 bit-matrix transpose across a warp (Hacker's Delight butterfly).
// Input: lane k holds word x (bit i = element (k, i)).
// Output: lane L's word has popc == column-sum for time (31 - L).
__device__ __forceinline__ unsigned bit_transpose32(unsigned x, int lane)
{
    unsigned m = 0x0000FFFFu;
    #pragma unroll
    for (int j = 16; j; j >>= 1) {
        unsigned y  = __shfl_xor_sync(0xffffffffu, x, j);
        unsigned lm = (lane & j) ? (m << j) : m;
        unsigned yy = (lane & j) ? (y << j) : (y >> j);
        x ^= (x ^ yy) & lm;
        m ^= m << (j >> 1);     // constant-folded under full unroll
    }
    return x;
}

// ---------------- single fused kernel: g + scan + u + y(FIR) + write -------------
// 128 blocks x 512 threads: block = (b, chunk) owns the full 1024-h row.
// Per epilogue group, ONE block barrier:
//   scan gg -> butterfly-transpose masks in regs -> store part+wsm -> B1
//   -> FIR warp computes y(gg)  ||  all warps write OUT(gg-1)  ||  scan gg+1
// Buffers: wsm %3 (read window and next write separated by a barrier),
// part &1, y &1, u_lin private to the rotating FIR warp (__syncwarp).
__global__ void __launch_bounds__(512) fused_kernel(const float* __restrict__ x,
                                                    const float* __restrict__ Ap,
                                                    const float* __restrict__ Bp,
                                                    const float* __restrict__ Cp,
                                                    const float* __restrict__ Dp,
                                                    float* __restrict__ out)
{
    __shared__ float As[64 * 65];        // A rows padded
    __shared__ float Wall[DMAX][64];     // Krylov vectors A^d B
    __shared__ float wping[2][64];
    __shared__ float cs[64];
    __shared__ float g_s[DMAX];
    __shared__ unsigned wsm[3][HID];     // triple-buffered group masks
    __shared__ int   part[2][16 * 32];   // double-buffered per-warp u partials
    __shared__ float u_lin[48];          // [0..15]=prev tail, [16..47]=cur group
    __shared__ float y_s[2][32], y1_s[2][32];

    const int blk  = blockIdx.x;         // 0..127
    const int c    = blk & (CHUNKS - 1);
    const int b    = blk >> 4;
    const int tid  = threadIdx.x;        // 0..511
    const int wid  = tid >> 5, lane = tid & 31;
    const int h    = tid * 2;            // 2 hidden lanes per thread

    const int warm    = c ? WGRP : 0;
    const int g0      = c * CGRP;
    const int tbegin  = (g0 - warm) * 32;
    const int ngroups = warm + CGRP;     // 8 or 14

    const float2* xp = (const float2*)(x + ((size_t)b * SEQ + tbegin) * HID) + tid;
    float4* out4 = (float4*)(out + ((size_t)b * SEQ + g0 * 32) * HID);
    const float Ds = __ldg(Dp);

    // issue the x prefetch FIRST so DRAM ramps under the g prologue.
    float2 buf[32];
    #pragma unroll
    for (int i = 0; i < 32; i++) buf[i] = xp[(size_t)i * HID2];
    const float2* xld = xp + (size_t)32 * HID2;

    // ---- g prologue: W_0=B; W_d=A W_{d-1}; g[d]=C.W_d ---------------------------
    for (int i = tid; i < 64 * 64; i += 512)
        As[(i >> 6) * 65 + (i & 63)] = Ap[i];
    if (tid < 64) {
        cs[tid] = Cp[tid];
        float b0 = Bp[tid];
        wping[0][tid] = b0;
        Wall[0][tid]  = b0;
    }
    if (tid >= 64 && tid < 80) u_lin[tid - 64] = 0.0f;   // halo for chunk 0
    __syncthreads();
    {
        const int row = tid >> 3, sub = tid & 7;         // 8 threads per row
        for (int d = 1; d < DMAX; d++) {
            const float* wprev = wping[(d - 1) & 1];
            float p = 0.f;
            #pragma unroll
            for (int j = 0; j < 8; j++)
                p += As[row * 65 + sub * 8 + j] * wprev[sub * 8 + j];
            p += __shfl_xor_sync(0xffffffffu, p, 1);
            p += __shfl_xor_sync(0xffffffffu, p, 2);
            p += __shfl_xor_sync(0xffffffffu, p, 4);
            if (sub == 0) { wping[d & 1][row] = p; Wall[d][row] = p; }
            __syncthreads();
        }
        if (tid < DMAX * 8) {                            // all 16 dots in parallel
            const int d = tid >> 3, s8 = (tid & 7) * 8;
            float p = 0.f;
            #pragma unroll
            for (int j = 0; j < 8; j++) p += cs[s8 + j] * Wall[d][s8 + j];
            p += __shfl_xor_sync(0xffffffffu, p, 1);
            p += __shfl_xor_sync(0xffffffffu, p, 2);
            p += __shfl_xor_sync(0xffffffffu, p, 4);
            if ((tid & 7) == 0) g_s[d] = p;
        }
        __syncthreads();
    }

    // ---- pipelined main loop: ONE barrier per epilogue group --------------------
    SnnState s0 = {0,1,1,0}, s1 = {0,1,1,0};

    for (int gg = 0; gg < ngroups; gg++) {
        const bool pf = (gg + 1 < ngroups);
        float m0l = 0, m0h = 0, m1l = 0, m1h = 0;
        #pragma unroll
        for (int i = 0; i < 32; i++) {
            float2 xk = buf[i];
            if (pf) buf[i] = xld[(size_t)i * HID2];      // prefetch next group
            const float mc = (float)(1u << (i & 15));
            if (i < 16) { snn_step(s0, xk.x, m0l, mc); snn_step(s1, xk.y, m1l, mc); }
            else        { snn_step(s0, xk.x, m0h, mc); snn_step(s1, xk.y, m1h, mc); }
        }
        xld += (size_t)32 * HID2;

        if (gg < warm - 1) continue;                     // uniform per block

        uint2 mv;
        mv.x = __float2uint_rn(m0l) | (__float2uint_rn(m0h) << 16);
        mv.y = __float2uint_rn(m1l) | (__float2uint_rn(m1h) << 16);

        // per-warp u partials in registers (no smem transpose, no barrier needed)
        unsigned tx = bit_transpose32(mv.x, lane);
        unsigned ty = bit_transpose32(mv.y, lane);
        part[gg & 1][wid * 32 + (31 ^ lane)] = __popc(tx) + __popc(ty);
        *(uint2*)&wsm[gg % 3][h] = mv;
        __syncthreads();                                 // B1: part+wsm(gg), y(gg-1)

        if (wid == (gg & 15)) {                          // rotating FIR warp
            const int* pb = part[gg & 1];
            int tot = 0;
            #pragma unroll
            for (int w2 = 0; w2 < 16; w2++) tot += pb[w2 * 32 + lane];
            float uv = (float)tot * (1.0f / (float)HID);
            u_lin[16 + lane] = uv;
            __syncwarp();                                // u_lin visible warp-wide
            if (gg >= warm) {
                float acc = Ds * uv;                     // y = D*u + g (*) u
                #pragma unroll
                for (int d = 0; d < DMAX; d++)
                    acc += g_s[d] * u_lin[16 + lane - d];
                y_s[gg & 1][lane]  = acc;
                y1_s[gg & 1][lane] = acc + 1.0f;
            }
            __syncwarp();                                // taps read before slide
            if (lane < 16) u_lin[lane] = u_lin[32 + lane];
        }

        if (gg - 1 >= warm) {                            // write OUT for group gg-1
            const unsigned* wprev = wsm[(gg + 2) % 3];   // == (gg-1) % 3
            const float* yb  = y_s[(gg - 1) & 1];
            const float* y1b = y1_s[(gg - 1) & 1];
            const int q  = tid & 255;
            const int hf = tid >> 8;
            const uint4 w4 = ((const uint4*)wprev)[q];
            float4* rowb = out4 + (size_t)(gg - 1 - warm) * 32 * HID4 + q;
            #pragma unroll
            for (int k = 0; k < 16; k++) {
                const int t = hf * 16 + k;
                const float y = yb[t], y1 = y1b[t];
                float4 o;
                o.x = ((w4.x >> t) & 1u) ? y1 : y;
                o.y = ((w4.y >> t) & 1u) ? y1 : y;
                o.z = ((w4.z >> t) & 1u) ? y1 : y;
                o.w = ((w4.w >> t) & 1u) ? y1 : y;
                __stcs(&rowb[(size_t)t * HID4], o);
            }
        }
    }

    // ---- drain: write OUT for the final group -----------------------------------
    __syncthreads();                                     // y[last] ready
    {
        const int lg = ngroups - 1;                      // always >= warm
        const unsigned* wprev = wsm[lg % 3];
        const float* yb  = y_s[lg & 1];
        const float* y1b = y1_s[lg & 1];
        const int q  = tid & 255;
        const int hf = tid >> 8;
        const uint4 w4 = ((const uint4*)wprev)[q];
        float4* rowb = out4 + (size_t)(lg - warm) * 32 * HID4 + q;
        #pragma unroll
        for (int k = 0; k < 16; k++) {
            const int t = hf * 16 + k;
            const float y = yb[t], y1 = y1b[t];
            float4 o;
            o.x = ((w4.x >> t) & 1u) ? y1 : y;
            o.y = ((w4.y >> t) & 1u) ? y1 : y;
            o.z = ((w4.z >> t) & 1u) ? y1 : y;
            o.w = ((w4.w >> t) & 1u) ? y1 : y;
            __stcs(&rowb[(size_t)t * HID4], o);
        }
    }
}

// ---------------- launch ----------------------------------------------------------
extern "C" void kernel_launch(void* const* d_in, const int* in_sizes, int n_in,
                              void* d_out, int out_size)
{
    const float* x  = (const float*)d_in[0];   // (8, 4096, 1024) f32
    const float* A  = (const float*)d_in[1];   // (64, 64)
    const float* Bv = (const float*)d_in[2];   // (64, 1)
    const float* Cv = (const float*)d_in[3];   // (1, 64)
    const float* Dp = (const float*)d_in[4];   // (1, 1)

    fused_kernel<<<B_SZ * CHUNKS, 512>>>(x, A, Bv, Cv, Dp, (float*)d_out);
}